// round 12
// baseline (speedup 1.0000x reference)
#include <cuda_runtime.h>
#include <cstddef>
#include <cstdint>

// Problem constants
#define B_   4
#define TQ_  512
#define TP_  512
#define D_   256

// ---------------------------------------------------------------------------
// Scratch (static device globals)
// ---------------------------------------------------------------------------
__device__ float g_pq[(size_t)B_ * TQ_ * D_];    // q @ W0  [B,Tq,D]
__device__ float g_pp[(size_t)B_ * TP_ * D_];    // p @ W1  [B,Tp,D]
__device__ float g_sc[(size_t)B_ * TP_ * TQ_];   // exp(scores) [B,Tp,Tq]
__device__ float g_cpart[B_ * 8 * TQ_];          // per-p-tile column partials
__device__ float g_part[2 * 1024 * 1024];        // 8MB split-K partials
__device__ unsigned int g_cntP[4 * 32 * 2];      // proj tile arrival counters
__device__ unsigned int g_cntO[4 * 8 * 4];       // out tile arrival counters

// ---------------------------------------------------------------------------
// fp32 HW tanh (1 MUFU op).
// ---------------------------------------------------------------------------
__device__ __forceinline__ float ftanh(float x) {
    float r;
    asm("tanh.approx.f32 %0, %1;" : "=f"(r) : "f"(x));
    return r;
}

__device__ __forceinline__ uint32_t f2tf32(float x) {
    uint32_t r;
    asm("cvt.rna.tf32.f32 %0, %1;" : "=r"(r) : "f"(x));
    return r;
}

__device__ __forceinline__ float4 ldcg4(const float4* p) {
    float4 v;
    asm volatile("ld.global.cg.v4.f32 {%0,%1,%2,%3}, [%4];"
                 : "=f"(v.x), "=f"(v.y), "=f"(v.z), "=f"(v.w) : "l"(p));
    return v;
}

// ---------------------------------------------------------------------------
// tf32 tensor-core GEMM slice (proven R6/R8 geometry).
// Block tile 64x64, BK=32, 256 threads = 8 warps (2m x 4n),
// warp tile 32x16: 2 m-frags x 2 n-frags of m16n8k8.
// C[M,N] (partial) = A[M, kbeg:kend] * B[kbeg:kend, N], both row-major.
// If SCALE, A column k is scaled by cs[k] at load (cs may be smem).
// ---------------------------------------------------------------------------
template <bool SCALE>
__device__ __forceinline__ void tf32_gemm_64x64(const float* __restrict__ A,
                                                const float* __restrict__ B,
                                                float* __restrict__ C,
                                                const float* cs,
                                                int N, int K, int kbeg, int kend,
                                                int m0, int n0) {
    __shared__ uint32_t As[64][36];  // [m][k]
    __shared__ uint32_t Bs[32][72];  // [k][n]

    const int tid = threadIdx.x;
    const int lane = tid & 31;
    const int w = tid >> 5;
    const int wm = (w >> 2) * 32;
    const int wn = (w & 3) * 16;
    const int frow = lane >> 2;
    const int fcol = lane & 3;

    float c[2][2][4];
#pragma unroll
    for (int mi = 0; mi < 2; mi++)
#pragma unroll
        for (int ni = 0; ni < 2; ni++)
#pragma unroll
            for (int k = 0; k < 4; k++) c[mi][ni][k] = 0.0f;

    float4 ra[2], rb[2];
    auto loadG = [&](int k0) {
#pragma unroll
        for (int s = 0; s < 2; s++) {
            int id = tid + s * 256;
            int r = id >> 3, cc = (id & 7) * 4;
            ra[s] = *(const float4*)&A[(size_t)(m0 + r) * K + k0 + cc];
            if (SCALE) {
                float4 sc = *(const float4*)&cs[k0 + cc];
                ra[s].x *= sc.x; ra[s].y *= sc.y;
                ra[s].z *= sc.z; ra[s].w *= sc.w;
            }
        }
#pragma unroll
        for (int s = 0; s < 2; s++) {
            int id = tid + s * 256;
            int r = id >> 4, cc = (id & 15) * 4;
            rb[s] = *(const float4*)&B[(size_t)(k0 + r) * N + n0 + cc];
        }
    };
    auto storeS = [&]() {
#pragma unroll
        for (int s = 0; s < 2; s++) {
            int id = tid + s * 256;
            int r = id >> 3, cc = (id & 7) * 4;
            As[r][cc + 0] = f2tf32(ra[s].x);
            As[r][cc + 1] = f2tf32(ra[s].y);
            As[r][cc + 2] = f2tf32(ra[s].z);
            As[r][cc + 3] = f2tf32(ra[s].w);
        }
#pragma unroll
        for (int s = 0; s < 2; s++) {
            int id = tid + s * 256;
            int r = id >> 4, cc = (id & 15) * 4;
            Bs[r][cc + 0] = f2tf32(rb[s].x);
            Bs[r][cc + 1] = f2tf32(rb[s].y);
            Bs[r][cc + 2] = f2tf32(rb[s].z);
            Bs[r][cc + 3] = f2tf32(rb[s].w);
        }
    };

    loadG(kbeg);
    for (int k0 = kbeg; k0 < kend; k0 += 32) {
        storeS();
        __syncthreads();
        if (k0 + 32 < kend) loadG(k0 + 32);
#pragma unroll
        for (int ks = 0; ks < 4; ks++) {
            const int kk = ks * 8;
            uint32_t a[2][4], bfr[2][2];
#pragma unroll
            for (int mi = 0; mi < 2; mi++) {
                a[mi][0] = As[wm + mi * 16 + frow][kk + fcol];
                a[mi][1] = As[wm + mi * 16 + frow + 8][kk + fcol];
                a[mi][2] = As[wm + mi * 16 + frow][kk + fcol + 4];
                a[mi][3] = As[wm + mi * 16 + frow + 8][kk + fcol + 4];
            }
#pragma unroll
            for (int ni = 0; ni < 2; ni++) {
                bfr[ni][0] = Bs[kk + fcol][wn + ni * 8 + frow];
                bfr[ni][1] = Bs[kk + fcol + 4][wn + ni * 8 + frow];
            }
#pragma unroll
            for (int mi = 0; mi < 2; mi++)
#pragma unroll
                for (int ni = 0; ni < 2; ni++)
                    asm volatile(
                        "mma.sync.aligned.m16n8k8.row.col.f32.tf32.tf32.f32 "
                        "{%0,%1,%2,%3},{%4,%5,%6,%7},{%8,%9},{%0,%1,%2,%3};"
                        : "+f"(c[mi][ni][0]), "+f"(c[mi][ni][1]),
                          "+f"(c[mi][ni][2]), "+f"(c[mi][ni][3])
                        : "r"(a[mi][0]), "r"(a[mi][1]), "r"(a[mi][2]),
                          "r"(a[mi][3]), "r"(bfr[ni][0]), "r"(bfr[ni][1]));
        }
        __syncthreads();
    }

#pragma unroll
    for (int mi = 0; mi < 2; mi++)
#pragma unroll
        for (int ni = 0; ni < 2; ni++) {
            int rr = m0 + wm + mi * 16 + frow;
            int cc = n0 + wn + ni * 8 + fcol * 2;
            *(float2*)&C[(size_t)rr * N + cc] =
                make_float2(c[mi][ni][0], c[mi][ni][1]);
            *(float2*)&C[(size_t)(rr + 8) * N + cc] =
                make_float2(c[mi][ni][2], c[mi][ni][3]);
        }
}

// ---------------------------------------------------------------------------
// Kernel 1: projections (tf32 TC), split-K=2, FUSED last-block reduce.
//   part[s*2+t] = (t?p:q)[:, ks:ks+128] @ (t?W1:W0)[ks:ks+128, :]
// The last block to finish a (tile, t) pair sums the two split partials in
// FIXED order (s0 + s1 -- deterministic) and writes g_pq / g_pp.
// grid (4, 32, 4) = 512 blocks.
// ---------------------------------------------------------------------------
__global__ __launch_bounds__(256) void proj_kernel(const float* __restrict__ q,
                                                   const float* __restrict__ p,
                                                   const float* __restrict__ W0,
                                                   const float* __restrict__ W1) {
    const int t = blockIdx.z & 1;
    const int s = blockIdx.z >> 1;
    const int m0 = blockIdx.y * 64;
    const int n0 = blockIdx.x * 64;
    const float* A = t ? p : q;
    const float* Bw = t ? W1 : W0;
    constexpr size_t NFT = (size_t)B_ * TQ_ * D_;
    float* C = g_part + (size_t)(s * 2 + t) * NFT;
    tf32_gemm_64x64<false>(A, Bw, C, nullptr, D_, D_,
                           s * 128, s * 128 + 128, m0, n0);

    __threadfence();
    __syncthreads();
    __shared__ int isLast;
    const int cidx = (blockIdx.x * 32 + blockIdx.y) * 2 + t;
    if (threadIdx.x == 0) {
        unsigned int old = atomicAdd(&g_cntP[cidx], 1u);
        isLast = (old == 1u);
    }
    __syncthreads();
    if (isLast) {
        if (threadIdx.x == 0) g_cntP[cidx] = 0u;  // self-clean for next launch
        const float4* P0 = (const float4*)(g_part + (size_t)(0 * 2 + t) * NFT);
        const float4* P1 = (const float4*)(g_part + (size_t)(1 * 2 + t) * NFT);
        float4* dst = (float4*)(t ? g_pp : g_pq);
#pragma unroll
        for (int k2 = 0; k2 < 4; k2++) {
            int id = threadIdx.x + k2 * 256;
            int r = id >> 4, cc = id & 15;
            size_t off = (size_t)(m0 + r) * (D_ / 4) + (n0 / 4) + cc;
            float4 a = ldcg4(&P0[off]);
            float4 b = ldcg4(&P1[off]);
            dst[off] = make_float4(a.x + b.x, a.y + b.y, a.z + b.z, a.w + b.w);
        }
    }
}

// ---------------------------------------------------------------------------
// Kernel 2: energies -> exp(score) + per-block column partial sums.
// fp32 MUFU.TANH, 64x64 tile, 4x4 micro -- at the MUFU throughput floor.
// DOUBLE-BUFFERED smem: next d-chunk's global loads issue before the MUFU
// loop of the current chunk, so global latency hides under ~14K cyc of MUFU
// work.  One __syncthreads per chunk.
// ---------------------------------------------------------------------------
__global__ __launch_bounds__(256) void energy_kernel(const float* __restrict__ vc) {
    __shared__ float sp[2][64][33];
    __shared__ float sq[2][64][33];
    __shared__ float sv[256];
    __shared__ float colred[16][64];

    const int b = blockIdx.z;
    const int p0 = blockIdx.y * 64;
    const int q0 = blockIdx.x * 64;
    const int tid = threadIdx.x;
    const int tx = tid & 15;
    const int ty = tid >> 4;

    const float* ppb = g_pp + ((size_t)b * TP_ + p0) * D_;
    const float* pqb = g_pq + ((size_t)b * TQ_ + q0) * D_;

    sv[tid] = vc[tid];  // 256 threads, D_=256 values

    float4 rP[2], rQ[2];
    auto loadG = [&](int d0) {
#pragma unroll
        for (int s = 0; s < 2; s++) {
            int id = tid + s * 256;
            int r = id >> 3, cc = (id & 7) * 4;
            rP[s] = *(const float4*)&ppb[(size_t)r * D_ + d0 + cc];
            rQ[s] = *(const float4*)&pqb[(size_t)r * D_ + d0 + cc];
        }
    };
    auto storeS = [&](int st) {
#pragma unroll
        for (int s = 0; s < 2; s++) {
            int id = tid + s * 256;
            int r = id >> 3, cc = (id & 7) * 4;
            sp[st][r][cc + 0] = rP[s].x; sp[st][r][cc + 1] = rP[s].y;
            sp[st][r][cc + 2] = rP[s].z; sp[st][r][cc + 3] = rP[s].w;
            sq[st][r][cc + 0] = rQ[s].x; sq[st][r][cc + 1] = rQ[s].y;
            sq[st][r][cc + 2] = rQ[s].z; sq[st][r][cc + 3] = rQ[s].w;
        }
    };

    float acc[4][4];
#pragma unroll
    for (int i = 0; i < 4; i++)
#pragma unroll
        for (int j = 0; j < 4; j++) acc[i][j] = 0.0f;

    loadG(0);
    storeS(0);
    __syncthreads();

#pragma unroll 1
    for (int ch = 0; ch < 8; ch++) {
        if (ch < 7) loadG((ch + 1) * 32);
        const int st = ch & 1;
#pragma unroll 8
        for (int d = 0; d < 32; d++) {
            float v = sv[ch * 32 + d];
            float a[4], bb[4];
#pragma unroll
            for (int i = 0; i < 4; i++) a[i] = sp[st][ty * 4 + i][d];
#pragma unroll
            for (int j = 0; j < 4; j++) bb[j] = sq[st][tx * 4 + j][d];
#pragma unroll
            for (int i = 0; i < 4; i++)
#pragma unroll
                for (int j = 0; j < 4; j++)
                    acc[i][j] = fmaf(v, ftanh(a[i] + bb[j]), acc[i][j]);
        }
        if (ch < 7) storeS((ch + 1) & 1);
        __syncthreads();
    }

    float colp[4] = {0.f, 0.f, 0.f, 0.f};
#pragma unroll
    for (int i = 0; i < 4; i++) {
        float4 o;
        o.x = __expf(acc[i][0]);
        o.y = __expf(acc[i][1]);
        o.z = __expf(acc[i][2]);
        o.w = __expf(acc[i][3]);
        colp[0] += o.x; colp[1] += o.y; colp[2] += o.z; colp[3] += o.w;
        *(float4*)&g_sc[((size_t)b * TP_ + p0 + ty * 4 + i) * TQ_ + q0 + tx * 4] = o;
    }
    *(float4*)&colred[ty][tx * 4] =
        make_float4(colp[0], colp[1], colp[2], colp[3]);
    __syncthreads();
    if (tid < 64) {
        float s = colred[0][tid];
#pragma unroll
        for (int t = 1; t < 16; t++) s += colred[t][tid];
        g_cpart[(b * 8 + blockIdx.y) * TQ_ + q0 + tid] = s;
    }
}

// ---------------------------------------------------------------------------
// Kernel 3: out GEMM (tf32 TC), split-K=4, in-block column-sum inverse +
// normalize fused into A load, FUSED last-block reduce writing d_out in
// FIXED order (s0+s1)+(s2+s3) -- deterministic, identical grouping to the
// old out_reduce kernel.  grid (4, 8, 16) = 512 blocks.
// ---------------------------------------------------------------------------
__global__ __launch_bounds__(256) void out_gemm_kernel(const float* __restrict__ qin,
                                                       float* __restrict__ out) {
    __shared__ __align__(16) float sinv[128];

    const int b = blockIdx.z & 3;
    const int s = blockIdx.z >> 2;
    const int kbeg = s * 128;
    const int m0 = blockIdx.y * 64;
    const int n0 = blockIdx.x * 64;
    const int tid = threadIdx.x;

    if (tid < 128) {
        const int qq = kbeg + tid;
        float sum = 0.f;
#pragma unroll
        for (int t = 0; t < 8; t++) sum += g_cpart[(b * 8 + t) * TQ_ + qq];
        sinv[tid] = __fdividef(1.0f, sum);
    }
    __syncthreads();

    float* C = g_part + (size_t)(s * 4 + b) * (TP_ * D_);
    tf32_gemm_64x64<true>(g_sc + (size_t)b * TP_ * TQ_,
                          qin + (size_t)b * TQ_ * D_, C,
                          sinv - kbeg, D_, TQ_,
                          kbeg, kbeg + 128, m0, n0);

    __threadfence();
    __syncthreads();
    __shared__ int isLast;
    const int cidx = (blockIdx.x * 8 + blockIdx.y) * 4 + b;
    if (tid == 0) {
        unsigned int old = atomicAdd(&g_cntO[cidx], 1u);
        isLast = (old == 3u);
    }
    __syncthreads();
    if (isLast) {
        if (tid == 0) g_cntO[cidx] = 0u;  // self-clean for next launch
        const float4* P[4];
#pragma unroll
        for (int s2 = 0; s2 < 4; s2++)
            P[s2] = (const float4*)(g_part + (size_t)(s2 * 4 + b) * (TP_ * D_));
        float4* dst = (float4*)out + (size_t)b * (TP_ * D_ / 4);
#pragma unroll
        for (int k2 = 0; k2 < 4; k2++) {
            int id = tid + k2 * 256;
            int r = id >> 4, cc = id & 15;
            size_t off = (size_t)(m0 + r) * (D_ / 4) + (n0 / 4) + cc;
            float4 v0 = ldcg4(&P[0][off]);
            float4 v1 = ldcg4(&P[1][off]);
            float4 v2 = ldcg4(&P[2][off]);
            float4 v3 = ldcg4(&P[3][off]);
            float4 rr;
            rr.x = (v0.x + v1.x) + (v2.x + v3.x);
            rr.y = (v0.y + v1.y) + (v2.y + v3.y);
            rr.z = (v0.z + v1.z) + (v2.z + v3.z);
            rr.w = (v0.w + v1.w) + (v2.w + v3.w);
            dst[off] = rr;
        }
    }
}

// ---------------------------------------------------------------------------
// Launch: 3 kernels, serial full-grid.  (Measured dead ends: multi-stream
// per-batch pipelining +4us; inline dual-partial reads in energy +12us;
// 128x64/BK=16 gemm tile +4us; f16x2 tanh 2-pass on MUFU, no gain.)
// ---------------------------------------------------------------------------
extern "C" void kernel_launch(void* const* d_in, const int* in_sizes, int n_in,
                              void* d_out, int out_size) {
    const float* q = (const float*)d_in[0];   // [B,Tq,D]
    const float* p = (const float*)d_in[1];   // [B,Tp,D]
    const float* W0 = (const float*)d_in[2];  // [D,D]
    const float* W1 = (const float*)d_in[3];  // [D,D]
    const float* vc = (const float*)d_in[4];  // [D,1]
    float* out = (float*)d_out;               // [B,Tp,D]

    // 1. Projections (tensor core, split-K=2, fused last-block reduce)
    {
        dim3 grid(D_ / 64, (B_ * TQ_) / 64, 4);
        proj_kernel<<<grid, 256>>>(q, p, W0, W1);
    }
    // 2. Energies -> exp(score) + column partials (double-buffered)
    {
        dim3 grid(TQ_ / 64, TP_ / 64, B_);
        energy_kernel<<<grid, 256>>>(vc);
    }
    // 3. Output GEMM (tensor core, split-K=4, in-block colsum + normalize,
    //    fused last-block reduce -> d_out)
    {
        dim3 grid(D_ / 64, TP_ / 64, 16);
        out_gemm_kernel<<<grid, 256>>>(q, out);
    }
}

// round 13
// speedup vs baseline: 1.0777x; 1.0777x over previous
#include <cuda_runtime.h>
#include <cstddef>
#include <cstdint>

// Problem constants
#define B_   4
#define TQ_  512
#define TP_  512
#define D_   256

// ---------------------------------------------------------------------------
// Scratch (static device globals)
// ---------------------------------------------------------------------------
__device__ float g_pq[(size_t)B_ * TQ_ * D_];    // q @ W0  [B,Tq,D]
__device__ float g_pp[(size_t)B_ * TP_ * D_];    // p @ W1  [B,Tp,D]
__device__ float g_sc[(size_t)B_ * TP_ * TQ_];   // exp(scores) [B,Tp,Tq]
__device__ float g_cpart[B_ * 8 * TQ_];          // per-p-tile column partials
__device__ float g_part[2 * 1024 * 1024];        // 8MB split-K partials

// ---------------------------------------------------------------------------
// fp32 HW tanh (1 MUFU op).
// ---------------------------------------------------------------------------
__device__ __forceinline__ float ftanh(float x) {
    float r;
    asm("tanh.approx.f32 %0, %1;" : "=f"(r) : "f"(x));
    return r;
}

__device__ __forceinline__ uint32_t f2tf32(float x) {
    uint32_t r;
    asm("cvt.rna.tf32.f32 %0, %1;" : "=r"(r) : "f"(x));
    return r;
}

// ---------------------------------------------------------------------------
// tf32 tensor-core GEMM slice (proven R6/R8 geometry).
// Block tile 64x64, BK=32, 256 threads = 8 warps (2m x 4n),
// warp tile 32x16: 2 m-frags x 2 n-frags of m16n8k8.
// C[M,N] (partial) = A[M, kbeg:kend] * B[kbeg:kend, N], both row-major.
// If SCALE, A column k is scaled by cs[k] at load (cs may be smem).
// ---------------------------------------------------------------------------
template <bool SCALE>
__device__ __forceinline__ void tf32_gemm_64x64(const float* __restrict__ A,
                                                const float* __restrict__ B,
                                                float* __restrict__ C,
                                                const float* cs,
                                                int N, int K, int kbeg, int kend,
                                                int m0, int n0) {
    __shared__ uint32_t As[64][36];  // [m][k]
    __shared__ uint32_t Bs[32][72];  // [k][n]

    const int tid = threadIdx.x;
    const int lane = tid & 31;
    const int w = tid >> 5;
    const int wm = (w >> 2) * 32;
    const int wn = (w & 3) * 16;
    const int frow = lane >> 2;
    const int fcol = lane & 3;

    float c[2][2][4];
#pragma unroll
    for (int mi = 0; mi < 2; mi++)
#pragma unroll
        for (int ni = 0; ni < 2; ni++)
#pragma unroll
            for (int k = 0; k < 4; k++) c[mi][ni][k] = 0.0f;

    float4 ra[2], rb[2];
    auto loadG = [&](int k0) {
#pragma unroll
        for (int s = 0; s < 2; s++) {
            int id = tid + s * 256;
            int r = id >> 3, cc = (id & 7) * 4;
            ra[s] = *(const float4*)&A[(size_t)(m0 + r) * K + k0 + cc];
            if (SCALE) {
                float4 sc = *(const float4*)&cs[k0 + cc];
                ra[s].x *= sc.x; ra[s].y *= sc.y;
                ra[s].z *= sc.z; ra[s].w *= sc.w;
            }
        }
#pragma unroll
        for (int s = 0; s < 2; s++) {
            int id = tid + s * 256;
            int r = id >> 4, cc = (id & 15) * 4;
            rb[s] = *(const float4*)&B[(size_t)(k0 + r) * N + n0 + cc];
        }
    };
    auto storeS = [&]() {
#pragma unroll
        for (int s = 0; s < 2; s++) {
            int id = tid + s * 256;
            int r = id >> 3, cc = (id & 7) * 4;
            As[r][cc + 0] = f2tf32(ra[s].x);
            As[r][cc + 1] = f2tf32(ra[s].y);
            As[r][cc + 2] = f2tf32(ra[s].z);
            As[r][cc + 3] = f2tf32(ra[s].w);
        }
#pragma unroll
        for (int s = 0; s < 2; s++) {
            int id = tid + s * 256;
            int r = id >> 4, cc = (id & 15) * 4;
            Bs[r][cc + 0] = f2tf32(rb[s].x);
            Bs[r][cc + 1] = f2tf32(rb[s].y);
            Bs[r][cc + 2] = f2tf32(rb[s].z);
            Bs[r][cc + 3] = f2tf32(rb[s].w);
        }
    };

    loadG(kbeg);
    for (int k0 = kbeg; k0 < kend; k0 += 32) {
        storeS();
        __syncthreads();
        if (k0 + 32 < kend) loadG(k0 + 32);
#pragma unroll
        for (int ks = 0; ks < 4; ks++) {
            const int kk = ks * 8;
            uint32_t a[2][4], bfr[2][2];
#pragma unroll
            for (int mi = 0; mi < 2; mi++) {
                a[mi][0] = As[wm + mi * 16 + frow][kk + fcol];
                a[mi][1] = As[wm + mi * 16 + frow + 8][kk + fcol];
                a[mi][2] = As[wm + mi * 16 + frow][kk + fcol + 4];
                a[mi][3] = As[wm + mi * 16 + frow + 8][kk + fcol + 4];
            }
#pragma unroll
            for (int ni = 0; ni < 2; ni++) {
                bfr[ni][0] = Bs[kk + fcol][wn + ni * 8 + frow];
                bfr[ni][1] = Bs[kk + fcol + 4][wn + ni * 8 + frow];
            }
#pragma unroll
            for (int mi = 0; mi < 2; mi++)
#pragma unroll
                for (int ni = 0; ni < 2; ni++)
                    asm volatile(
                        "mma.sync.aligned.m16n8k8.row.col.f32.tf32.tf32.f32 "
                        "{%0,%1,%2,%3},{%4,%5,%6,%7},{%8,%9},{%0,%1,%2,%3};"
                        : "+f"(c[mi][ni][0]), "+f"(c[mi][ni][1]),
                          "+f"(c[mi][ni][2]), "+f"(c[mi][ni][3])
                        : "r"(a[mi][0]), "r"(a[mi][1]), "r"(a[mi][2]),
                          "r"(a[mi][3]), "r"(bfr[ni][0]), "r"(bfr[ni][1]));
        }
        __syncthreads();
    }

#pragma unroll
    for (int mi = 0; mi < 2; mi++)
#pragma unroll
        for (int ni = 0; ni < 2; ni++) {
            int rr = m0 + wm + mi * 16 + frow;
            int cc = n0 + wn + ni * 8 + fcol * 2;
            *(float2*)&C[(size_t)rr * N + cc] =
                make_float2(c[mi][ni][0], c[mi][ni][1]);
            *(float2*)&C[(size_t)(rr + 8) * N + cc] =
                make_float2(c[mi][ni][2], c[mi][ni][3]);
        }
}

// ---------------------------------------------------------------------------
// Kernel 1: projections (tf32 TC), split-K=2.  z = t + 2*s.
//   part[s*2+t] = (t?p:q)[:, ks:ks+128] @ (t?W1:W0)[ks:ks+128, :]
// grid (4, 32, 4) = 512 blocks.
// ---------------------------------------------------------------------------
__global__ __launch_bounds__(256) void proj_kernel(const float* __restrict__ q,
                                                   const float* __restrict__ p,
                                                   const float* __restrict__ W0,
                                                   const float* __restrict__ W1) {
    const int t = blockIdx.z & 1;
    const int s = blockIdx.z >> 1;
    const float* A = t ? p : q;
    const float* Bw = t ? W1 : W0;
    float* C = g_part + (size_t)(s * 2 + t) * (B_ * TQ_ * D_);
    tf32_gemm_64x64<false>(A, Bw, C, nullptr, D_, D_,
                           s * 128, s * 128 + 128,
                           blockIdx.y * 64, blockIdx.x * 64);
}

// Reduce proj partials -> g_pq (t=0), g_pp (t=1).  (R8 version.)
__global__ __launch_bounds__(256) void proj_reduce_kernel() {
    const int i = blockIdx.x * 256 + threadIdx.x;  // float4 index
    constexpr int NF4 = (B_ * TQ_ * D_) / 4;       // per tensor
    const int t = (i < NF4) ? 0 : 1;
    const int j = (t == 0) ? i : (i - NF4);
    const float4* p0 = (const float4*)g_part + (size_t)(0 * 2 + t) * NF4 + j;
    const float4* p1 = (const float4*)g_part + (size_t)(1 * 2 + t) * NF4 + j;
    float4 a = *p0, b = *p1;
    float4 r = make_float4(a.x + b.x, a.y + b.y, a.z + b.z, a.w + b.w);
    float4* dst = (float4*)(t ? g_pp : g_pq) + j;
    *dst = r;
}

// ---------------------------------------------------------------------------
// Kernel 2: energies -> exp(score) + per-block column partial sums.
// fp32 MUFU.TANH, 64x64 tile, 4x4 micro.  DOUBLE-BUFFERED smem: chunk k+1's
// global loads issue before chunk k's ~14K-cycle MUFU loop, hiding global
// latency.  One __syncthreads per chunk (was two).
// ---------------------------------------------------------------------------
__global__ __launch_bounds__(256) void energy_kernel(const float* __restrict__ vc) {
    __shared__ float sp[2][64][33];
    __shared__ float sq[2][64][33];
    __shared__ float sv[256];
    __shared__ float colred[16][64];

    const int b = blockIdx.z;
    const int p0 = blockIdx.y * 64;
    const int q0 = blockIdx.x * 64;
    const int tid = threadIdx.x;
    const int tx = tid & 15;
    const int ty = tid >> 4;

    const float* ppb = g_pp + ((size_t)b * TP_ + p0) * D_;
    const float* pqb = g_pq + ((size_t)b * TQ_ + q0) * D_;

    sv[tid] = vc[tid];  // 256 threads, D_=256 values

    float4 rP[2], rQ[2];
    auto loadG = [&](int d0) {
#pragma unroll
        for (int s = 0; s < 2; s++) {
            int id = tid + s * 256;
            int r = id >> 3, cc = (id & 7) * 4;
            rP[s] = *(const float4*)&ppb[(size_t)r * D_ + d0 + cc];
            rQ[s] = *(const float4*)&pqb[(size_t)r * D_ + d0 + cc];
        }
    };
    auto storeS = [&](int st) {
#pragma unroll
        for (int s = 0; s < 2; s++) {
            int id = tid + s * 256;
            int r = id >> 3, cc = (id & 7) * 4;
            sp[st][r][cc + 0] = rP[s].x; sp[st][r][cc + 1] = rP[s].y;
            sp[st][r][cc + 2] = rP[s].z; sp[st][r][cc + 3] = rP[s].w;
            sq[st][r][cc + 0] = rQ[s].x; sq[st][r][cc + 1] = rQ[s].y;
            sq[st][r][cc + 2] = rQ[s].z; sq[st][r][cc + 3] = rQ[s].w;
        }
    };

    float acc[4][4];
#pragma unroll
    for (int i = 0; i < 4; i++)
#pragma unroll
        for (int j = 0; j < 4; j++) acc[i][j] = 0.0f;

    loadG(0);
    storeS(0);
    __syncthreads();

#pragma unroll 1
    for (int ch = 0; ch < 8; ch++) {
        if (ch < 7) loadG((ch + 1) * 32);
        const int st = ch & 1;
#pragma unroll 8
        for (int d = 0; d < 32; d++) {
            float v = sv[ch * 32 + d];
            float a[4], bb[4];
#pragma unroll
            for (int i = 0; i < 4; i++) a[i] = sp[st][ty * 4 + i][d];
#pragma unroll
            for (int j = 0; j < 4; j++) bb[j] = sq[st][tx * 4 + j][d];
#pragma unroll
            for (int i = 0; i < 4; i++)
#pragma unroll
                for (int j = 0; j < 4; j++)
                    acc[i][j] = fmaf(v, ftanh(a[i] + bb[j]), acc[i][j]);
        }
        if (ch < 7) storeS((ch + 1) & 1);
        __syncthreads();
    }

    float colp[4] = {0.f, 0.f, 0.f, 0.f};
#pragma unroll
    for (int i = 0; i < 4; i++) {
        float4 o;
        o.x = __expf(acc[i][0]);
        o.y = __expf(acc[i][1]);
        o.z = __expf(acc[i][2]);
        o.w = __expf(acc[i][3]);
        colp[0] += o.x; colp[1] += o.y; colp[2] += o.z; colp[3] += o.w;
        *(float4*)&g_sc[((size_t)b * TP_ + p0 + ty * 4 + i) * TQ_ + q0 + tx * 4] = o;
    }
    *(float4*)&colred[ty][tx * 4] =
        make_float4(colp[0], colp[1], colp[2], colp[3]);
    __syncthreads();
    if (tid < 64) {
        float s = colred[0][tid];
#pragma unroll
        for (int t = 1; t < 16; t++) s += colred[t][tid];
        g_cpart[(b * 8 + blockIdx.y) * TQ_ + q0 + tid] = s;
    }
}

// ---------------------------------------------------------------------------
// Kernel 3: out GEMM (tf32 TC), split-K=4, in-block column-sum inverse +
// normalize fused into A load.  grid (4, 8, 16) = 512 blocks.  (R8 version.)
// ---------------------------------------------------------------------------
__global__ __launch_bounds__(256) void out_gemm_kernel(const float* __restrict__ qin) {
    __shared__ __align__(16) float sinv[128];

    const int b = blockIdx.z & 3;
    const int s = blockIdx.z >> 2;
    const int kbeg = s * 128;
    const int tid = threadIdx.x;

    if (tid < 128) {
        const int qq = kbeg + tid;
        float sum = 0.f;
#pragma unroll
        for (int t = 0; t < 8; t++) sum += g_cpart[(b * 8 + t) * TQ_ + qq];
        sinv[tid] = __fdividef(1.0f, sum);
    }
    __syncthreads();

    float* C = g_part + (size_t)(s * 4 + b) * (TP_ * D_);
    tf32_gemm_64x64<true>(g_sc + (size_t)b * TP_ * TQ_,
                          qin + (size_t)b * TQ_ * D_, C,
                          sinv - kbeg, D_, TQ_,
                          kbeg, kbeg + 128,
                          blockIdx.y * 64, blockIdx.x * 64);
}

// Reduce out partials: out = sum over 4 splits.  Deterministic.  (R8 version.)
__global__ __launch_bounds__(256) void out_reduce_kernel(float* __restrict__ out) {
    const int i = blockIdx.x * 256 + threadIdx.x;  // float4 idx
    constexpr int NB4 = (TP_ * D_) / 4;
    const int b = i / NB4;
    const int j = i % NB4;
    float4 r = make_float4(0.f, 0.f, 0.f, 0.f);
#pragma unroll
    for (int s = 0; s < 4; s++) {
        float4 v = *((const float4*)g_part + (size_t)(s * 4 + b) * NB4 + j);
        r.x += v.x; r.y += v.y; r.z += v.z; r.w += v.w;
    }
    *((float4*)out + i) = r;
}

// ---------------------------------------------------------------------------
// Launch: R8's proven serial full-grid schedule; only the energy kernel
// changed (double-buffered).  Measured dead ends: multi-stream per-batch
// pipelining +4us; inline dual-partial reads in energy +12us; 128x64/BK=16
// gemm tile +4us; fused last-block reduces (threadfence) +7us on proj;
// f16x2 tanh 2-pass on MUFU, no gain.
// ---------------------------------------------------------------------------
extern "C" void kernel_launch(void* const* d_in, const int* in_sizes, int n_in,
                              void* d_out, int out_size) {
    const float* q = (const float*)d_in[0];   // [B,Tq,D]
    const float* p = (const float*)d_in[1];   // [B,Tp,D]
    const float* W0 = (const float*)d_in[2];  // [D,D]
    const float* W1 = (const float*)d_in[3];  // [D,D]
    const float* vc = (const float*)d_in[4];  // [D,1]
    float* out = (float*)d_out;               // [B,Tp,D]

    // 1. Projections (tensor core, split-K=2) + reduce
    {
        dim3 grid(D_ / 64, (B_ * TQ_) / 64, 4);
        proj_kernel<<<grid, 256>>>(q, p, W0, W1);
        proj_reduce_kernel<<<(2 * B_ * TQ_ * D_ / 4) / 256, 256>>>();
    }
    // 2. Energies -> exp(score) + column partials (double-buffered)
    {
        dim3 grid(TQ_ / 64, TP_ / 64, B_);
        energy_kernel<<<grid, 256>>>(vc);
    }
    // 3. Output GEMM (tensor core, split-K=4, in-block colsum + normalize)
    {
        dim3 grid(D_ / 64, TP_ / 64, 16);
        out_gemm_kernel<<<grid, 256>>>(q);
        out_reduce_kernel<<<(B_ * TP_ * D_ / 4) / 256, 256>>>(out);
    }
}

// round 14
// speedup vs baseline: 1.0918x; 1.0131x over previous
#include <cuda_runtime.h>
#include <cstddef>
#include <cstdint>

// Problem constants
#define B_   4
#define TQ_  512
#define TP_  512
#define D_   256

// ---------------------------------------------------------------------------
// Scratch (static device globals)
// ---------------------------------------------------------------------------
__device__ float g_pq[(size_t)B_ * TQ_ * D_];    // q @ W0  [B,Tq,D]
__device__ float g_pp[(size_t)B_ * TP_ * D_];    // p @ W1  [B,Tp,D]
__device__ float g_sc[(size_t)B_ * TP_ * TQ_];   // exp(scores) [B,Tp,Tq]
__device__ float g_cpart[B_ * 8 * TQ_];          // per-p-tile column partials
__device__ float g_part[2 * 1024 * 1024];        // 8MB split-K partials

// ---------------------------------------------------------------------------
// fp32 HW tanh (1 MUFU op).
// ---------------------------------------------------------------------------
__device__ __forceinline__ float ftanh(float x) {
    float r;
    asm("tanh.approx.f32 %0, %1;" : "=f"(r) : "f"(x));
    return r;
}

__device__ __forceinline__ uint32_t f2tf32(float x) {
    uint32_t r;
    asm("cvt.rna.tf32.f32 %0, %1;" : "=r"(r) : "f"(x));
    return r;
}

// ---------------------------------------------------------------------------
// tf32 tensor-core GEMM slice.  Block tile 64x128, BK=32, single-buffered
// (proven), 256 threads = 8 warps (2m x 4n), warp tile 32x32:
// 2 m-frags x 4 n-frags of m16n8k8 -> 8 MMAs per 16 LDS (2x the old ratio).
// C[M,N] (partial) = A[M, kbeg:kend] * B[kbeg:kend, N], both row-major.
// If SCALE, A column k is scaled by cs[k] at load (cs may be smem).
// ---------------------------------------------------------------------------
template <bool SCALE>
__device__ __forceinline__ void tf32_gemm_64x128(const float* __restrict__ A,
                                                 const float* __restrict__ B,
                                                 float* __restrict__ C,
                                                 const float* cs,
                                                 int N, int K, int kbeg, int kend,
                                                 int m0, int n0) {
    __shared__ uint32_t As[64][36];   // [m][k]  36-stride: conflict-free frags
    __shared__ uint32_t Bs[32][136];  // [k][n] 136-stride: conflict-free frags

    const int tid = threadIdx.x;
    const int lane = tid & 31;
    const int w = tid >> 5;
    const int wm = (w >> 2) * 32;   // 0 / 32
    const int wn = (w & 3) * 32;    // 0 / 32 / 64 / 96
    const int frow = lane >> 2;     // 0..7
    const int fcol = lane & 3;      // 0..3

    float c[2][4][4];
#pragma unroll
    for (int mi = 0; mi < 2; mi++)
#pragma unroll
        for (int ni = 0; ni < 4; ni++)
#pragma unroll
            for (int k = 0; k < 4; k++) c[mi][ni][k] = 0.0f;

    // A tile 64x32 = 512 float4 (2/thread); B tile 32x128 = 1024 float4 (4/thread)
    float4 ra[2], rb[4];
    auto loadG = [&](int k0) {
#pragma unroll
        for (int s = 0; s < 2; s++) {
            int id = tid + s * 256;
            int r = id >> 3, cc = (id & 7) * 4;
            ra[s] = *(const float4*)&A[(size_t)(m0 + r) * K + k0 + cc];
            if (SCALE) {
                float4 sc = *(const float4*)&cs[k0 + cc];
                ra[s].x *= sc.x; ra[s].y *= sc.y;
                ra[s].z *= sc.z; ra[s].w *= sc.w;
            }
        }
#pragma unroll
        for (int s = 0; s < 4; s++) {
            int id = tid + s * 256;
            int r = id >> 5, cc = (id & 31) * 4;
            rb[s] = *(const float4*)&B[(size_t)(k0 + r) * N + n0 + cc];
        }
    };
    auto storeS = [&]() {
#pragma unroll
        for (int s = 0; s < 2; s++) {
            int id = tid + s * 256;
            int r = id >> 3, cc = (id & 7) * 4;
            As[r][cc + 0] = f2tf32(ra[s].x);
            As[r][cc + 1] = f2tf32(ra[s].y);
            As[r][cc + 2] = f2tf32(ra[s].z);
            As[r][cc + 3] = f2tf32(ra[s].w);
        }
#pragma unroll
        for (int s = 0; s < 4; s++) {
            int id = tid + s * 256;
            int r = id >> 5, cc = (id & 31) * 4;
            Bs[r][cc + 0] = f2tf32(rb[s].x);
            Bs[r][cc + 1] = f2tf32(rb[s].y);
            Bs[r][cc + 2] = f2tf32(rb[s].z);
            Bs[r][cc + 3] = f2tf32(rb[s].w);
        }
    };

    loadG(kbeg);
    for (int k0 = kbeg; k0 < kend; k0 += 32) {
        storeS();
        __syncthreads();
        if (k0 + 32 < kend) loadG(k0 + 32);
#pragma unroll
        for (int ks = 0; ks < 4; ks++) {
            const int kk = ks * 8;
            uint32_t a[2][4], bfr[4][2];
#pragma unroll
            for (int mi = 0; mi < 2; mi++) {
                a[mi][0] = As[wm + mi * 16 + frow][kk + fcol];
                a[mi][1] = As[wm + mi * 16 + frow + 8][kk + fcol];
                a[mi][2] = As[wm + mi * 16 + frow][kk + fcol + 4];
                a[mi][3] = As[wm + mi * 16 + frow + 8][kk + fcol + 4];
            }
#pragma unroll
            for (int ni = 0; ni < 4; ni++) {
                bfr[ni][0] = Bs[kk + fcol][wn + ni * 8 + frow];
                bfr[ni][1] = Bs[kk + fcol + 4][wn + ni * 8 + frow];
            }
#pragma unroll
            for (int mi = 0; mi < 2; mi++)
#pragma unroll
                for (int ni = 0; ni < 4; ni++)
                    asm volatile(
                        "mma.sync.aligned.m16n8k8.row.col.f32.tf32.tf32.f32 "
                        "{%0,%1,%2,%3},{%4,%5,%6,%7},{%8,%9},{%0,%1,%2,%3};"
                        : "+f"(c[mi][ni][0]), "+f"(c[mi][ni][1]),
                          "+f"(c[mi][ni][2]), "+f"(c[mi][ni][3])
                        : "r"(a[mi][0]), "r"(a[mi][1]), "r"(a[mi][2]),
                          "r"(a[mi][3]), "r"(bfr[ni][0]), "r"(bfr[ni][1]));
        }
        __syncthreads();
    }

#pragma unroll
    for (int mi = 0; mi < 2; mi++)
#pragma unroll
        for (int ni = 0; ni < 4; ni++) {
            int rr = m0 + wm + mi * 16 + frow;
            int cc = n0 + wn + ni * 8 + fcol * 2;
            *(float2*)&C[(size_t)rr * N + cc] =
                make_float2(c[mi][ni][0], c[mi][ni][1]);
            *(float2*)&C[(size_t)(rr + 8) * N + cc] =
                make_float2(c[mi][ni][2], c[mi][ni][3]);
        }
}

// ---------------------------------------------------------------------------
// Kernel 1: projections (tf32 TC), split-K=2.  z = t + 2*s.
//   part[s*2+t] = (t?p:q)[:, ks:ks+128] @ (t?W1:W0)[ks:ks+128, :]
// grid (2, 32, 4) = 256 blocks.
// ---------------------------------------------------------------------------
__global__ __launch_bounds__(256) void proj_kernel(const float* __restrict__ q,
                                                   const float* __restrict__ p,
                                                   const float* __restrict__ W0,
                                                   const float* __restrict__ W1) {
    const int t = blockIdx.z & 1;
    const int s = blockIdx.z >> 1;
    const float* A = t ? p : q;
    const float* Bw = t ? W1 : W0;
    float* C = g_part + (size_t)(s * 2 + t) * (B_ * TQ_ * D_);
    tf32_gemm_64x128<false>(A, Bw, C, nullptr, D_, D_,
                            s * 128, s * 128 + 128,
                            blockIdx.y * 64, blockIdx.x * 128);
}

// Reduce proj partials -> g_pq (t=0), g_pp (t=1).
__global__ __launch_bounds__(256) void proj_reduce_kernel() {
    const int i = blockIdx.x * 256 + threadIdx.x;  // float4 index
    constexpr int NF4 = (B_ * TQ_ * D_) / 4;       // per tensor
    const int t = (i < NF4) ? 0 : 1;
    const int j = (t == 0) ? i : (i - NF4);
    const float4* p0 = (const float4*)g_part + (size_t)(0 * 2 + t) * NF4 + j;
    const float4* p1 = (const float4*)g_part + (size_t)(1 * 2 + t) * NF4 + j;
    float4 a = *p0, b = *p1;
    float4 r = make_float4(a.x + b.x, a.y + b.y, a.z + b.z, a.w + b.w);
    float4* dst = (float4*)(t ? g_pp : g_pq) + j;
    *dst = r;
}

// ---------------------------------------------------------------------------
// Kernel 2: energies -> exp(score) + per-block column partial sums.
// fp32 MUFU.TANH, 64x64 tile, 4x4 micro -- confirmed AT the MUFU floor
// (double-buffering measured exactly neutral; kept for the saved syncs).
// ---------------------------------------------------------------------------
__global__ __launch_bounds__(256) void energy_kernel(const float* __restrict__ vc) {
    __shared__ float sp[2][64][33];
    __shared__ float sq[2][64][33];
    __shared__ float sv[256];
    __shared__ float colred[16][64];

    const int b = blockIdx.z;
    const int p0 = blockIdx.y * 64;
    const int q0 = blockIdx.x * 64;
    const int tid = threadIdx.x;
    const int tx = tid & 15;
    const int ty = tid >> 4;

    const float* ppb = g_pp + ((size_t)b * TP_ + p0) * D_;
    const float* pqb = g_pq + ((size_t)b * TQ_ + q0) * D_;

    sv[tid] = vc[tid];

    float4 rP[2], rQ[2];
    auto loadG = [&](int d0) {
#pragma unroll
        for (int s = 0; s < 2; s++) {
            int id = tid + s * 256;
            int r = id >> 3, cc = (id & 7) * 4;
            rP[s] = *(const float4*)&ppb[(size_t)r * D_ + d0 + cc];
            rQ[s] = *(const float4*)&pqb[(size_t)r * D_ + d0 + cc];
        }
    };
    auto storeS = [&](int st) {
#pragma unroll
        for (int s = 0; s < 2; s++) {
            int id = tid + s * 256;
            int r = id >> 3, cc = (id & 7) * 4;
            sp[st][r][cc + 0] = rP[s].x; sp[st][r][cc + 1] = rP[s].y;
            sp[st][r][cc + 2] = rP[s].z; sp[st][r][cc + 3] = rP[s].w;
            sq[st][r][cc + 0] = rQ[s].x; sq[st][r][cc + 1] = rQ[s].y;
            sq[st][r][cc + 2] = rQ[s].z; sq[st][r][cc + 3] = rQ[s].w;
        }
    };

    float acc[4][4];
#pragma unroll
    for (int i = 0; i < 4; i++)
#pragma unroll
        for (int j = 0; j < 4; j++) acc[i][j] = 0.0f;

    loadG(0);
    storeS(0);
    __syncthreads();

#pragma unroll 1
    for (int ch = 0; ch < 8; ch++) {
        if (ch < 7) loadG((ch + 1) * 32);
        const int st = ch & 1;
#pragma unroll 8
        for (int d = 0; d < 32; d++) {
            float v = sv[ch * 32 + d];
            float a[4], bb[4];
#pragma unroll
            for (int i = 0; i < 4; i++) a[i] = sp[st][ty * 4 + i][d];
#pragma unroll
            for (int j = 0; j < 4; j++) bb[j] = sq[st][tx * 4 + j][d];
#pragma unroll
            for (int i = 0; i < 4; i++)
#pragma unroll
                for (int j = 0; j < 4; j++)
                    acc[i][j] = fmaf(v, ftanh(a[i] + bb[j]), acc[i][j]);
        }
        if (ch < 7) storeS((ch + 1) & 1);
        __syncthreads();
    }

    float colp[4] = {0.f, 0.f, 0.f, 0.f};
#pragma unroll
    for (int i = 0; i < 4; i++) {
        float4 o;
        o.x = __expf(acc[i][0]);
        o.y = __expf(acc[i][1]);
        o.z = __expf(acc[i][2]);
        o.w = __expf(acc[i][3]);
        colp[0] += o.x; colp[1] += o.y; colp[2] += o.z; colp[3] += o.w;
        *(float4*)&g_sc[((size_t)b * TP_ + p0 + ty * 4 + i) * TQ_ + q0 + tx * 4] = o;
    }
    *(float4*)&colred[ty][tx * 4] =
        make_float4(colp[0], colp[1], colp[2], colp[3]);
    __syncthreads();
    if (tid < 64) {
        float s = colred[0][tid];
#pragma unroll
        for (int t = 1; t < 16; t++) s += colred[t][tid];
        g_cpart[(b * 8 + blockIdx.y) * TQ_ + q0 + tid] = s;
    }
}

// ---------------------------------------------------------------------------
// Kernel 3: out GEMM (tf32 TC), split-K=4, in-block column-sum inverse +
// normalize fused into A load.  grid (2, 8, 16) = 256 blocks.
// ---------------------------------------------------------------------------
__global__ __launch_bounds__(256) void out_gemm_kernel(const float* __restrict__ qin) {
    __shared__ __align__(16) float sinv[128];

    const int b = blockIdx.z & 3;
    const int s = blockIdx.z >> 2;
    const int kbeg = s * 128;
    const int tid = threadIdx.x;

    if (tid < 128) {
        const int qq = kbeg + tid;
        float sum = 0.f;
#pragma unroll
        for (int t = 0; t < 8; t++) sum += g_cpart[(b * 8 + t) * TQ_ + qq];
        sinv[tid] = __fdividef(1.0f, sum);
    }
    __syncthreads();

    float* C = g_part + (size_t)(s * 4 + b) * (TP_ * D_);
    tf32_gemm_64x128<true>(g_sc + (size_t)b * TP_ * TQ_,
                           qin + (size_t)b * TQ_ * D_, C,
                           sinv - kbeg, D_, TQ_,
                           kbeg, kbeg + 128,
                           blockIdx.y * 64, blockIdx.x * 128);
}

// Reduce out partials: out = sum over 4 splits.  Deterministic.
__global__ __launch_bounds__(256) void out_reduce_kernel(float* __restrict__ out) {
    const int i = blockIdx.x * 256 + threadIdx.x;  // float4 idx
    constexpr int NB4 = (TP_ * D_) / 4;
    const int b = i / NB4;
    const int j = i % NB4;
    float4 r = make_float4(0.f, 0.f, 0.f, 0.f);
#pragma unroll
    for (int s = 0; s < 4; s++) {
        float4 v = *((const float4*)g_part + (size_t)(s * 4 + b) * NB4 + j);
        r.x += v.x; r.y += v.y; r.z += v.z; r.w += v.w;
    }
    *((float4*)out + i) = r;
}

// ---------------------------------------------------------------------------
// Launch.  Measured dead ends: multi-stream per-batch pipelining +4us;
// inline dual-partial reads in energy +12us; 128x64/BK=16 double-buffered
// gemm tile +4us; fused last-block reduces (threadfence) +7us; f16x2 tanh
// 2-pass on MUFU, no gain; energy double-buffer neutral (already hidden).
// ---------------------------------------------------------------------------
extern "C" void kernel_launch(void* const* d_in, const int* in_sizes, int n_in,
                              void* d_out, int out_size) {
    const float* q = (const float*)d_in[0];   // [B,Tq,D]
    const float* p = (const float*)d_in[1];   // [B,Tp,D]
    const float* W0 = (const float*)d_in[2];  // [D,D]
    const float* W1 = (const float*)d_in[3];  // [D,D]
    const float* vc = (const float*)d_in[4];  // [D,1]
    float* out = (float*)d_out;               // [B,Tp,D]

    // 1. Projections (tensor core, split-K=2) + reduce
    {
        dim3 grid(D_ / 128, (B_ * TQ_) / 64, 4);
        proj_kernel<<<grid, 256>>>(q, p, W0, W1);
        proj_reduce_kernel<<<(2 * B_ * TQ_ * D_ / 4) / 256, 256>>>();
    }
    // 2. Energies -> exp(score) + column partials
    {
        dim3 grid(TQ_ / 64, TP_ / 64, B_);
        energy_kernel<<<grid, 256>>>(vc);
    }
    // 3. Output GEMM (tensor core, split-K=4, in-block colsum + normalize)
    {
        dim3 grid(D_ / 128, TP_ / 64, 16);
        out_gemm_kernel<<<grid, 256>>>(q);
        out_reduce_kernel<<<(B_ * TP_ * D_ / 4) / 256, 256>>>(out);
    }
}